// round 11
// baseline (speedup 1.0000x reference)
#include <cuda_runtime.h>
#include <cuda_bf16.h>

// GaussianModel: cov = (R*diag(s)) (R*diag(s))^T per Gaussian, N=4M.
// Inputs: rotation_raw float32 [N,4], scaling_raw float32 [N,3]
// Output: cov float32 [N,3,3]
//
// R10: kernel sits on the mixed read/write HBM floor (in-kernel 40.7us vs
// ~42us theoretical; DRAM=62% with L2 absorbing the tail of the write
// stream). Only structural slack left: overlap compute and stores inside
// each warp. Software-pipeline: compute elem0 -> store elem0's half-tile ->
// compute elem1 -> store second half. Access patterns unchanged (all
// contiguous float4, warp-private smem, __syncwarp only).

__device__ __forceinline__ void cov_one(float4 q, float a0, float a1, float a2,
                                        float* __restrict__ o /* 9 floats */)
{
    float w = q.x, x = q.y, y = q.z, z = q.w;

    // R is quadratic in the normalized quaternion: fold 2/||q||^2 into the
    // cross terms instead of normalizing.
    float n2   = w*w + x*x + y*y + z*z;
    float inv2 = __fdividef(2.0f, n2);

    float xx = x*x*inv2, yy = y*y*inv2, zz = z*z*inv2;
    float xy = x*y*inv2, xz = x*z*inv2, yz = y*z*inv2;
    float wx = w*x*inv2, wy = w*y*inv2, wz = w*z*inv2;

    float r00 = 1.0f - yy - zz, r01 = xy - wz,        r02 = xz + wy;
    float r10 = xy + wz,        r11 = 1.0f - xx - zz, r12 = yz - wx;
    float r20 = xz - wy,        r21 = yz + wx,        r22 = 1.0f - xx - yy;

    // s_k^2 = exp(2 * raw_k)
    float s00 = __expf(2.0f * a0);
    float s11 = __expf(2.0f * a1);
    float s22 = __expf(2.0f * a2);

    float c00 = r00*r00*s00 + r01*r01*s11 + r02*r02*s22;
    float c01 = r00*r10*s00 + r01*r11*s11 + r02*r12*s22;
    float c02 = r00*r20*s00 + r01*r21*s11 + r02*r22*s22;
    float c11 = r10*r10*s00 + r11*r11*s11 + r12*r12*s22;
    float c12 = r10*r20*s00 + r11*r21*s11 + r12*r22*s22;
    float c22 = r20*r20*s00 + r21*r21*s11 + r22*r22*s22;

    // STS.32 stride-9: gcd(9,32)=1 -> conflict-free
    o[0] = c00; o[1] = c01; o[2] = c02;
    o[3] = c01; o[4] = c11; o[5] = c12;
    o[6] = c02; o[7] = c12; o[8] = c22;
}

__global__ __launch_bounds__(256)
void gaussian_cov_kernel(const float4* __restrict__ rot,
                         const float*  __restrict__ sc,
                         float*        __restrict__ out,
                         int n)
{
    // Warp-private slices: 8 warps x (192 scale floats + 576 out floats)
    __shared__ float sh_s[8][192];   //  6 KB
    __shared__ float sh_o[8][576];   // 18 KB

    const int tid  = threadIdx.x;
    const int wrp  = tid >> 5;
    const int lane = tid & 31;
    const int base = blockIdx.x * 512;

    if (base + 512 <= n) {
        // ============ guardless warp-autonomous fast path ============
        const int eb = base + 64 * wrp;        // this warp's 64 elements

        // Front-batch global reads: 2 quat LDG.128 + scale staging.
        float4 q0 = __ldcs(&rot[eb + lane]);
        float4 q1 = __ldcs(&rot[eb + 32 + lane]);

        {   // 192 scale floats = 48 float4 at sc + 3*eb (3*eb % 4 == 0)
            const float4* s4 = (const float4*)(sc + 3 * eb);
            float4* sh4 = (float4*)sh_s[wrp];
            sh4[lane] = __ldcs(&s4[lane]);
            if (lane < 16) sh4[32 + lane] = __ldcs(&s4[32 + lane]);
        }
        __syncwarp();

        const float*  ss  = sh_s[wrp];
        float*        so  = sh_o[wrp];
        float4*       dst = (float4*)(out + 9 * eb);   // 144 float4 total
        const float4* src = (const float4*)so;

        // --- stage A: compute elems [0,32), store their 72 float4 ---
        // floats 0..287 of the tile == outputs of elems 0..31 exactly.
        cov_one(q0, ss[3*lane], ss[3*lane+1], ss[3*lane+2], so + 9*lane);
        __syncwarp();
        __stcs(&dst[lane],      src[lane]);
        __stcs(&dst[lane + 32], src[lane + 32]);
        if (lane < 8)
            __stcs(&dst[lane + 64], src[lane + 64]);

        // --- stage B: compute elems [32,64), store float4 72..143 ---
        {
            int l = lane + 32;
            cov_one(q1, ss[3*l], ss[3*l+1], ss[3*l+2], so + 9*l);
        }
        __syncwarp();
        __stcs(&dst[lane + 72],  src[lane + 72]);
        __stcs(&dst[lane + 104], src[lane + 104]);
        if (lane < 8)
            __stcs(&dst[lane + 136], src[lane + 136]);
    } else {
        // ============ guarded tail path (last partial block) =========
        #pragma unroll
        for (int e = 0; e < 2; e++) {
            int i = base + tid + 256 * e;
            if (i < n) {
                float4 q = __ldg(&rot[i]);
                float c[9];
                cov_one(q, __ldg(sc + 3*i), __ldg(sc + 3*i + 1),
                        __ldg(sc + 3*i + 2), c);
                float* o = out + 9 * i;
                #pragma unroll
                for (int k = 0; k < 9; k++) o[k] = c[k];
            }
        }
    }
}

extern "C" void kernel_launch(void* const* d_in, const int* in_sizes, int n_in,
                              void* d_out, int out_size)
{
    const float4* rot = (const float4*)d_in[0];   // [N,4] float32
    const float*  sc  = (const float*) d_in[1];   // [N,3] float32
    float*        out = (float*)d_out;            // [N,3,3] float32

    int n  = in_sizes[0] / 4;
    int nb = (n + 511) / 512;
    gaussian_cov_kernel<<<nb, 256>>>(rot, sc, out, n);
}

// round 12
// speedup vs baseline: 1.1140x; 1.1140x over previous
#include <cuda_runtime.h>
#include <cuda_bf16.h>

// GaussianModel: cov = (R*diag(s)) (R*diag(s))^T per Gaussian, N=4M.
// Inputs: rotation_raw float32 [N,4], scaling_raw float32 [N,3]
// Output: cov float32 [N,3,3]
//
// R11: all prior variants front-batch <=3.5 LDG.128/lane; DRAM stuck at 62%
// with nothing saturated => exposed DRAM latency. Double the warp tile to
// 128 elems (4/thread): 7 LDG.128/lane in flight before the first use.
// Output smem buffer reused across two compute->store phases so smem stays
// 30 KB/block (occupancy unchanged). All global traffic remains contiguous
// float4; warp-autonomous; __syncwarp only.

__device__ __forceinline__ void cov_one(float4 q, float a0, float a1, float a2,
                                        float* __restrict__ o /* 9 floats */)
{
    float w = q.x, x = q.y, y = q.z, z = q.w;

    // R is quadratic in the normalized quaternion: fold 2/||q||^2 into the
    // cross terms instead of normalizing.
    float n2   = w*w + x*x + y*y + z*z;
    float inv2 = __fdividef(2.0f, n2);

    float xx = x*x*inv2, yy = y*y*inv2, zz = z*z*inv2;
    float xy = x*y*inv2, xz = x*z*inv2, yz = y*z*inv2;
    float wx = w*x*inv2, wy = w*y*inv2, wz = w*z*inv2;

    float r00 = 1.0f - yy - zz, r01 = xy - wz,        r02 = xz + wy;
    float r10 = xy + wz,        r11 = 1.0f - xx - zz, r12 = yz - wx;
    float r20 = xz - wy,        r21 = yz + wx,        r22 = 1.0f - xx - yy;

    // s_k^2 = exp(2 * raw_k)
    float s00 = __expf(2.0f * a0);
    float s11 = __expf(2.0f * a1);
    float s22 = __expf(2.0f * a2);

    float c00 = r00*r00*s00 + r01*r01*s11 + r02*r02*s22;
    float c01 = r00*r10*s00 + r01*r11*s11 + r02*r12*s22;
    float c02 = r00*r20*s00 + r01*r21*s11 + r02*r22*s22;
    float c11 = r10*r10*s00 + r11*r11*s11 + r12*r12*s22;
    float c12 = r10*r20*s00 + r11*r21*s11 + r12*r22*s22;
    float c22 = r20*r20*s00 + r21*r21*s11 + r22*r22*s22;

    // STS.32 stride-9: gcd(9,32)=1 -> conflict-free
    o[0] = c00; o[1] = c01; o[2] = c02;
    o[3] = c01; o[4] = c11; o[5] = c12;
    o[6] = c02; o[7] = c12; o[8] = c22;
}

__global__ __launch_bounds__(256)
void gaussian_cov_kernel(const float4* __restrict__ rot,
                         const float*  __restrict__ sc,
                         float*        __restrict__ out,
                         int n)
{
    // Per-warp: 384 scale floats (128 elems) + 576-float out buffer (reused
    // across two 64-elem phases). 8 warps: 12 KB + 18 KB = 30 KB/block.
    __shared__ float sh_s[8][384];
    __shared__ float sh_o[8][576];

    const int tid  = threadIdx.x;
    const int wrp  = tid >> 5;
    const int lane = tid & 31;
    const int base = blockIdx.x * 1024;

    if (base + 1024 <= n) {
        // ============ guardless warp-autonomous fast path ============
        const int eb = base + 128 * wrp;       // this warp's 128 elements

        // ---- Front-batch 7 LDG.128 per lane (max MLP) ----
        float4 q0 = __ldcs(&rot[eb + lane]);
        float4 q1 = __ldcs(&rot[eb + 32 + lane]);
        float4 q2 = __ldcs(&rot[eb + 64 + lane]);
        float4 q3 = __ldcs(&rot[eb + 96 + lane]);

        {   // 384 scale floats = 96 float4 at sc + 3*eb (3*eb % 4 == 0)
            const float4* s4 = (const float4*)(sc + 3 * eb);
            float4* sh4 = (float4*)sh_s[wrp];
            sh4[lane]      = __ldcs(&s4[lane]);
            sh4[lane + 32] = __ldcs(&s4[lane + 32]);
            sh4[lane + 64] = __ldcs(&s4[lane + 64]);
        }
        __syncwarp();

        const float*  ss  = sh_s[wrp];
        float*        so  = sh_o[wrp];
        float4*       dst = (float4*)(out + 9 * eb);   // 288 float4 total
        const float4* src = (const float4*)so;

        // ---- Phase A: elems [0,64) -> store float4 [0,144) ----
        {
            int l = lane;
            cov_one(q0, ss[3*l], ss[3*l+1], ss[3*l+2], so + 9*l);
            l = lane + 32;
            cov_one(q1, ss[3*l], ss[3*l+1], ss[3*l+2], so + 9*l);
        }
        __syncwarp();
        __stcs(&dst[lane],       src[lane]);
        __stcs(&dst[lane +  32], src[lane +  32]);
        __stcs(&dst[lane +  64], src[lane +  64]);
        __stcs(&dst[lane +  96], src[lane +  96]);
        if (lane < 16)
            __stcs(&dst[lane + 128], src[lane + 128]);
        // In-warp program order guarantees phase-A LDS precede phase-B STS;
        // buffer reuse below is safe.

        // ---- Phase B: elems [64,128) -> store float4 [144,288) ----
        {
            int l = lane;                       // buffer slot 0..31
            cov_one(q2, ss[3*(64+l)], ss[3*(64+l)+1], ss[3*(64+l)+2], so + 9*l);
            cov_one(q3, ss[3*(96+l)], ss[3*(96+l)+1], ss[3*(96+l)+2],
                    so + 9*(l + 32));
        }
        __syncwarp();
        __stcs(&dst[lane + 144], src[lane]);
        __stcs(&dst[lane + 176], src[lane +  32]);
        __stcs(&dst[lane + 208], src[lane +  64]);
        __stcs(&dst[lane + 240], src[lane +  96]);
        if (lane < 16)
            __stcs(&dst[lane + 272], src[lane + 128]);
    } else {
        // ============ guarded tail path (last partial block) =========
        #pragma unroll
        for (int e = 0; e < 4; e++) {
            int i = base + tid + 256 * e;
            if (i < n) {
                float4 q = __ldg(&rot[i]);
                float c[9];
                cov_one(q, __ldg(sc + 3*i), __ldg(sc + 3*i + 1),
                        __ldg(sc + 3*i + 2), c);
                float* o = out + 9 * i;
                #pragma unroll
                for (int k = 0; k < 9; k++) o[k] = c[k];
            }
        }
    }
}

extern "C" void kernel_launch(void* const* d_in, const int* in_sizes, int n_in,
                              void* d_out, int out_size)
{
    const float4* rot = (const float4*)d_in[0];   // [N,4] float32
    const float*  sc  = (const float*) d_in[1];   // [N,3] float32
    float*        out = (float*)d_out;            // [N,3,3] float32

    int n  = in_sizes[0] / 4;
    int nb = (n + 1023) / 1024;
    gaussian_cov_kernel<<<nb, 256>>>(rot, sc, out, n);
}